// round 3
// baseline (speedup 1.0000x reference)
#include <cuda_runtime.h>

#define NP 50000          // N_PROT
#define ND 5000           // N_DRUG
#define EPP 1600000
#define EPD 200000
#define INP 128           // IN_PROT / IN_DRUG
#define D1 64
#define D2 32
#define OUTD 64

#define SCAN_T 1024
#define SCAN_C ((NP + SCAN_T - 1) / SCAN_T)   // 49

// ---------------- scratch (device globals: no allocation allowed) ----------------
__device__ int   g_deg[NP];
__device__ float g_dinv[NP];
__device__ int   g_off[NP + 1];    // CSR row offsets (by dst)
__device__ int   g_pos[NP];        // placement cursors
__device__ int   g_esrc[EPP];      // CSR: src node per slot
__device__ float g_ew[EPP];        // CSR: edge weight per slot
__device__ float g_h1[NP * D1];    // x_prot @ W1 (raw)
__device__ float g_o1[NP * D1];    // propagated layer-1 output (pre-relu)
__device__ float g_h2[NP * D2];    // relu(o1) @ W2 (raw)
__device__ float g_agg[ND * D2];
__device__ float g_cnt[ND];

// ---------------- vector reduction helper (sm_90+) ----------------
__device__ __forceinline__ void red_add_v4(float* p, float x, float y, float z, float w) {
    asm volatile("red.global.add.v4.f32 [%0], {%1,%2,%3,%4};"
                 :: "l"(p), "f"(x), "f"(y), "f"(z), "f"(w) : "memory");
}

// ---------------- init / degree ----------------
__global__ void k_zero() {
    int gid = blockIdx.x * blockDim.x + threadIdx.x;
    int stride = gridDim.x * blockDim.x;
    for (int i = gid; i < NP; i += stride) g_deg[i] = 0;
    for (int i = gid; i < ND * D2; i += stride) g_agg[i] = 0.f;
    for (int i = gid; i < ND; i += stride) g_cnt[i] = 0.f;
}

__global__ void k_degree(const int* __restrict__ dst) {
    int e = blockIdx.x * blockDim.x + threadIdx.x;
    if (e < EPP) atomicAdd(&g_deg[dst[e]], 1);
}

__global__ void k_dinv() {
    int i = blockIdx.x * blockDim.x + threadIdx.x;
    if (i < NP) g_dinv[i] = rsqrtf((float)g_deg[i] + 1.0f);  // +1 = self loop
}

// ---------------- single-block hierarchical exclusive scan of g_deg -> g_off/g_pos ----------------
__global__ void __launch_bounds__(SCAN_T)
k_scan() {
    __shared__ int part[SCAN_T];
    const int t = threadIdx.x;
    const int lo = t * SCAN_C;
    const int hi = min(lo + SCAN_C, NP);
    int s = 0;
    for (int i = lo; i < hi; i++) s += g_deg[i];
    part[t] = s;
    __syncthreads();
    // inclusive scan over 1024 partials
    for (int ofs = 1; ofs < SCAN_T; ofs <<= 1) {
        int v = (t >= ofs) ? part[t - ofs] : 0;
        __syncthreads();
        part[t] += v;
        __syncthreads();
    }
    int run = part[t] - s;   // exclusive base for this thread's chunk
    for (int i = lo; i < hi; i++) {
        g_off[i] = run;
        g_pos[i] = run;
        run += g_deg[i];
    }
    if (t == 0) g_off[NP] = EPP;
}

// ---------------- placement: counting-sort edges by dst, weight fused ----------------
__global__ void k_place(const int* __restrict__ src, const int* __restrict__ dst) {
    int e = blockIdx.x * blockDim.x + threadIdx.x;
    if (e >= EPP) return;
    int s = src[e], d = dst[e];
    int p = atomicAdd(&g_pos[d], 1);
    g_esrc[p] = s;
    g_ew[p] = g_dinv[s] * g_dinv[d];
}

// ---------------- GEMM: Yraw = (RELU? relu(X) : X) @ W ----------------
template <int K, int M, int KC, bool RELU>
__global__ void __launch_bounds__(256)
k_gemm(const float* __restrict__ X, const float* __restrict__ W,
       float* __restrict__ Yraw, int N) {
    constexpr int CG  = M / 4;          // col groups
    constexpr int RG  = 256 / CG;       // row groups
    constexpr int RPB = RG * 4;         // rows per block
    constexpr int KCP = KC + 2;
    __shared__ float Ws[K * M];
    __shared__ float Xs[RPB][KCP];

    const int tid = threadIdx.x;
    for (int i = tid; i < K * M; i += 256) Ws[i] = W[i];

    const int row0 = blockIdx.x * RPB;
    const int cg = tid % CG, rg = tid / CG;
    const int c0 = cg * 4, r0 = rg * 4;
    float acc[4][4];
#pragma unroll
    for (int j = 0; j < 4; j++)
#pragma unroll
        for (int i = 0; i < 4; i++) acc[j][i] = 0.f;

    for (int kc0 = 0; kc0 < K; kc0 += KC) {
        constexpr int NV = RPB * KC / 4;
#pragma unroll
        for (int v = 0; v < NV / 256; v++) {
            int idx = tid + v * 256;
            int r = idx / (KC / 4), kq = idx % (KC / 4);
            int gr = row0 + r;
            float4 x = make_float4(0.f, 0.f, 0.f, 0.f);
            if (gr < N) x = *(const float4*)&X[(long long)gr * K + kc0 + kq * 4];
            if (RELU) {
                x.x = fmaxf(x.x, 0.f); x.y = fmaxf(x.y, 0.f);
                x.z = fmaxf(x.z, 0.f); x.w = fmaxf(x.w, 0.f);
            }
            Xs[r][kq * 4 + 0] = x.x; Xs[r][kq * 4 + 1] = x.y;
            Xs[r][kq * 4 + 2] = x.z; Xs[r][kq * 4 + 3] = x.w;
        }
        __syncthreads();
#pragma unroll 4
        for (int k = 0; k < KC; k++) {
            float4 wb = *(const float4*)&Ws[(kc0 + k) * M + c0];
#pragma unroll
            for (int j = 0; j < 4; j++) {
                float xa = Xs[r0 + j][k];
                acc[j][0] = fmaf(xa, wb.x, acc[j][0]);
                acc[j][1] = fmaf(xa, wb.y, acc[j][1]);
                acc[j][2] = fmaf(xa, wb.z, acc[j][2]);
                acc[j][3] = fmaf(xa, wb.w, acc[j][3]);
            }
        }
        __syncthreads();
    }

#pragma unroll
    for (int j = 0; j < 4; j++) {
        int gr = row0 + r0 + j;
        if (gr < N)
            *(float4*)&Yraw[(long long)gr * M + c0] =
                make_float4(acc[j][0], acc[j][1], acc[j][2], acc[j][3]);
    }
}

// ---------------- CSR gather: out[d] = b + dinv[d]^2*hin[d] + sum_e w[e]*hin[src[e]] ----------------
// One warp per destination row. M=64: 2 cols/lane. M=32: 1 col/lane.
template <int M>
__global__ void __launch_bounds__(256)
k_gather(const float* __restrict__ hin, const float* __restrict__ bias,
         float* __restrict__ hout) {
    const int warp = (blockIdx.x * blockDim.x + threadIdx.x) >> 5;
    if (warp >= NP) return;
    const int lane = threadIdx.x & 31;
    const int beg = g_off[warp], end = g_off[warp + 1];

    if (M == 64) {
        float a0 = 0.f, a1 = 0.f;
        int e = beg;
        for (; e + 1 < end; e += 2) {
            int s0 = g_esrc[e];     float w0 = g_ew[e];
            int s1 = g_esrc[e + 1]; float w1 = g_ew[e + 1];
            float x00 = hin[s0 * 64 + lane],      x01 = hin[s0 * 64 + 32 + lane];
            float x10 = hin[s1 * 64 + lane],      x11 = hin[s1 * 64 + 32 + lane];
            a0 = fmaf(w0, x00, a0); a1 = fmaf(w0, x01, a1);
            a0 = fmaf(w1, x10, a0); a1 = fmaf(w1, x11, a1);
        }
        if (e < end) {
            int s = g_esrc[e]; float w = g_ew[e];
            a0 = fmaf(w, hin[s * 64 + lane], a0);
            a1 = fmaf(w, hin[s * 64 + 32 + lane], a1);
        }
        float di = g_dinv[warp], d2 = di * di;
        a0 += bias[lane]      + d2 * hin[warp * 64 + lane];
        a1 += bias[32 + lane] + d2 * hin[warp * 64 + 32 + lane];
        hout[warp * 64 + lane]      = a0;
        hout[warp * 64 + 32 + lane] = a1;
    } else {
        float a0 = 0.f;
        int e = beg;
        for (; e + 1 < end; e += 2) {
            int s0 = g_esrc[e];     float w0 = g_ew[e];
            int s1 = g_esrc[e + 1]; float w1 = g_ew[e + 1];
            a0 = fmaf(w0, hin[s0 * 32 + lane], a0);
            a0 = fmaf(w1, hin[s1 * 32 + lane], a0);
        }
        if (e < end) a0 = fmaf(g_ew[e], hin[g_esrc[e] * 32 + lane], a0);
        float di = g_dinv[warp], d2 = di * di;
        a0 += bias[lane] + d2 * hin[warp * 32 + lane];
        hout[warp * 32 + lane] = a0;
    }
}

// ---------------- drug aggregation (atomic; small) ----------------
__global__ void __launch_bounds__(256)
k_drug_agg(const int* __restrict__ pds, const int* __restrict__ pdd,
           const float* __restrict__ h) {
    int gid = blockIdx.x * blockDim.x + threadIdx.x;
    int e = gid / (D2 / 4);
    if (e >= EPD) return;
    int c = (gid % (D2 / 4)) * 4;
    int s = pds[e], d = pdd[e];
    float4 hv = *(const float4*)&h[s * D2 + c];
    red_add_v4(&g_agg[d * D2 + c], hv.x, hv.y, hv.z, hv.w);
    if (c == 0) atomicAdd(&g_cnt[d], 1.0f);
}

// ---------------- final drug GEMM: out = mean @ Wl + bl + x_drug @ Wr ----------------
__global__ void __launch_bounds__(256)
k_drug_out(const float* __restrict__ xd, const float* __restrict__ Wl,
           const float* __restrict__ bl, const float* __restrict__ Wr,
           float* __restrict__ out) {
    __shared__ float Wls[D2 * OUTD];
    __shared__ float Wrs[INP * OUTD];
    __shared__ float bls[OUTD];
    __shared__ float Ms[4 * D2];
    __shared__ float Xs[4 * INP];
    const int tid = threadIdx.x;
    for (int i = tid; i < D2 * OUTD; i += 256) Wls[i] = Wl[i];
    for (int i = tid; i < INP * OUTD; i += 256) Wrs[i] = Wr[i];
    if (tid < OUTD) bls[tid] = bl[tid];
    const int row0 = blockIdx.x * 4;
    for (int i = tid; i < 4 * D2; i += 256) {
        int r = row0 + i / D2;
        float cnt = fmaxf(g_cnt[r], 1.0f);
        Ms[i] = g_agg[r * D2 + (i % D2)] / cnt;
    }
    for (int i = tid; i < 4 * INP; i += 256)
        Xs[i] = xd[(row0 + i / INP) * INP + (i % INP)];
    __syncthreads();
    const int c = tid % OUTD;
    const int r = tid / OUTD;
    float acc = bls[c];
#pragma unroll
    for (int k = 0; k < D2; k++) acc = fmaf(Ms[r * D2 + k], Wls[k * OUTD + c], acc);
#pragma unroll 8
    for (int k = 0; k < INP; k++) acc = fmaf(Xs[r * INP + k], Wrs[k * OUTD + c], acc);
    out[(row0 + r) * OUTD + c] = acc;
}

// ---------------- host ----------------
extern "C" void kernel_launch(void* const* d_in, const int* in_sizes, int n_in,
                              void* d_out, int out_size) {
    const float *x_prot = 0, *x_drug = 0, *W1 = 0, *b1 = 0, *W2 = 0, *b2 = 0;
    const float *Wl = 0, *bl = 0, *Wr = 0;
    const int *pp = 0, *pds = 0, *pdd = 0;
    int n200k = 0, n8192 = 0, n64 = 0, n2048 = 0;
    for (int i = 0; i < n_in; i++) {
        int s = in_sizes[i];
        void* p = d_in[i];
        if (s == NP * INP)        x_prot = (const float*)p;
        else if (s == ND * INP)   x_drug = (const float*)p;
        else if (s == 2 * EPP)    pp = (const int*)p;
        else if (s == EPD) {      if (n200k++ == 0) pds = (const int*)p; else pdd = (const int*)p; }
        else if (s == INP * D1) { if (n8192++ == 0) W1 = (const float*)p; else Wr = (const float*)p; }
        else if (s == D1) {       if (n64++   == 0) b1 = (const float*)p; else bl = (const float*)p; }
        else if (s == D1 * D2) {  if (n2048++ == 0) W2 = (const float*)p; else Wl = (const float*)p; }
        else if (s == D2)         b2 = (const float*)p;
    }
    const int* pp_src = pp;
    const int* pp_dst = pp + EPP;
    float* h_out = (float*)d_out;                  // [NP, D2]
    float* drug_out = h_out + (long long)NP * D2;  // [ND, OUTD]

    float* g_h1_p; cudaGetSymbolAddress((void**)&g_h1_p, g_h1);
    float* g_o1_p; cudaGetSymbolAddress((void**)&g_o1_p, g_o1);
    float* g_h2_p; cudaGetSymbolAddress((void**)&g_h2_p, g_h2);

    // CSR build: degree -> dinv -> scan -> place (weights fused)
    k_zero<<<256, 256>>>();
    k_degree<<<(EPP + 255) / 256, 256>>>(pp_dst);
    k_dinv<<<(NP + 255) / 256, 256>>>();
    k_scan<<<1, SCAN_T>>>();
    k_place<<<(EPP + 255) / 256, 256>>>(pp_src, pp_dst);

    // layer 1: gemm -> warp-per-row CSR gather (self-loop + bias fused)
    k_gemm<INP, D1, 32, false><<<(NP + 63) / 64, 256>>>(x_prot, W1, g_h1_p, NP);
    k_gather<D1><<<(NP * 32 + 255) / 256, 256>>>(g_h1_p, b1, g_o1_p);

    // layer 2: relu fused into gemm load -> gather straight into d_out
    k_gemm<D1, D2, 64, true><<<(NP + 127) / 128, 256>>>(g_o1_p, W2, g_h2_p, NP);
    k_gather<D2><<<(NP * 32 + 255) / 256, 256>>>(g_h2_p, b2, h_out);

    // bipartite mean-SAGE
    k_drug_agg<<<(EPD * (D2 / 4) + 255) / 256, 256>>>(pds, pdd, h_out);
    k_drug_out<<<ND / 4, 256>>>(x_drug, Wl, bl, Wr, drug_out);

    (void)out_size;
}

// round 4
// speedup vs baseline: 1.4467x; 1.4467x over previous
#include <cuda_runtime.h>

#define NP 50000          // N_PROT
#define ND 5000           // N_DRUG
#define EPP 1600000
#define EPD 200000
#define INP 128           // IN_PROT / IN_DRUG
#define D1 64
#define D2 32
#define OUTD 64

#define SB 256                          // scan block size
#define NB ((NP + SB - 1) / SB)         // 196 scan blocks

// ---------------- scratch (device globals: no allocation allowed) ----------------
__device__ int   g_deg[NP];
__device__ float g_dinv[NP];
__device__ int   g_bsum[NB];       // per-block degree sums
__device__ int   g_boff[NB];       // exclusive block offsets
__device__ int   g_off[NP + 1];    // CSR row offsets (by dst)
__device__ int   g_pos[NP];        // placement cursors
__device__ int2  g_edge[EPP];      // CSR: {src, bitcast(weight)}
__device__ float g_h1[NP * D1];    // x_prot @ W1 (raw)
__device__ float g_o1[NP * D1];    // propagated layer-1 output (pre-relu)
__device__ float g_h2[NP * D2];    // relu(o1) @ W2 (raw)
__device__ float g_agg[ND * D2];
__device__ float g_cnt[ND];

// ---------------- vector reduction helper (sm_90+) ----------------
__device__ __forceinline__ void red_add_v4(float* p, float x, float y, float z, float w) {
    asm volatile("red.global.add.v4.f32 [%0], {%1,%2,%3,%4};"
                 :: "l"(p), "f"(x), "f"(y), "f"(z), "f"(w) : "memory");
}

// ---------------- init / degree ----------------
__global__ void k_zero() {
    int gid = blockIdx.x * blockDim.x + threadIdx.x;
    int stride = gridDim.x * blockDim.x;
    for (int i = gid; i < NP; i += stride) g_deg[i] = 0;
    for (int i = gid; i < ND * D2; i += stride) g_agg[i] = 0.f;
    for (int i = gid; i < ND; i += stride) g_cnt[i] = 0.f;
}

__global__ void k_degree(const int* __restrict__ dst) {
    int e = blockIdx.x * blockDim.x + threadIdx.x;
    if (e < EPP) atomicAdd(&g_deg[dst[e]], 1);
}

// ---------------- 3-phase full-chip exclusive scan of g_deg ----------------
// Phase 1: per-block sums
__global__ void __launch_bounds__(SB) k_scan1() {
    __shared__ int sh[SB / 32];
    int i = blockIdx.x * SB + threadIdx.x;
    int v = (i < NP) ? g_deg[i] : 0;
#pragma unroll
    for (int o = 16; o > 0; o >>= 1) v += __shfl_down_sync(0xffffffffu, v, o);
    if ((threadIdx.x & 31) == 0) sh[threadIdx.x >> 5] = v;
    __syncthreads();
    if (threadIdx.x < SB / 32) {
        int w = sh[threadIdx.x];
#pragma unroll
        for (int o = SB / 64; o > 0; o >>= 1) w += __shfl_down_sync(0xffffffffu, w, o);
        if (threadIdx.x == 0) g_bsum[blockIdx.x] = w;
    }
}

// Phase 2: one block scans NB partials (NB <= 256)
__global__ void __launch_bounds__(SB) k_scan2() {
    __shared__ int sh[SB];
    int t = threadIdx.x;
    int v = (t < NB) ? g_bsum[t] : 0;
    sh[t] = v;
    __syncthreads();
    for (int o = 1; o < SB; o <<= 1) {
        int u = (t >= o) ? sh[t - o] : 0;
        __syncthreads();
        sh[t] += u;
        __syncthreads();
    }
    if (t < NB) g_boff[t] = sh[t] - v;   // exclusive
}

// Phase 3: local exclusive scan + block offset; fused dinv
__global__ void __launch_bounds__(SB) k_scan3() {
    __shared__ int sh[SB];
    int t = threadIdx.x;
    int i = blockIdx.x * SB + t;
    int v = (i < NP) ? g_deg[i] : 0;
    sh[t] = v;
    __syncthreads();
    for (int o = 1; o < SB; o <<= 1) {
        int u = (t >= o) ? sh[t - o] : 0;
        __syncthreads();
        sh[t] += u;
        __syncthreads();
    }
    if (i < NP) {
        int off = g_boff[blockIdx.x] + sh[t] - v;
        g_off[i] = off;
        g_pos[i] = off;
        g_dinv[i] = rsqrtf((float)v + 1.0f);   // +1 = self loop
    }
    if (i == NP - 1) g_off[NP] = EPP;
}

// ---------------- placement: counting-sort edges by dst, weight fused ----------------
__global__ void k_place(const int* __restrict__ src, const int* __restrict__ dst) {
    int e = blockIdx.x * blockDim.x + threadIdx.x;
    if (e >= EPP) return;
    int s = src[e], d = dst[e];
    int p = atomicAdd(&g_pos[d], 1);
    g_edge[p] = make_int2(s, __float_as_int(g_dinv[s] * g_dinv[d]));
}

// ---------------- GEMM: Yraw = (RELU? relu(X) : X) @ W ----------------
template <int K, int M, int KC, bool RELU>
__global__ void __launch_bounds__(256)
k_gemm(const float* __restrict__ X, const float* __restrict__ W,
       float* __restrict__ Yraw, int N) {
    constexpr int CG  = M / 4;
    constexpr int RG  = 256 / CG;
    constexpr int RPB = RG * 4;
    constexpr int KCP = KC + 2;
    __shared__ float Ws[K * M];
    __shared__ float Xs[RPB][KCP];

    const int tid = threadIdx.x;
    for (int i = tid; i < K * M; i += 256) Ws[i] = W[i];

    const int row0 = blockIdx.x * RPB;
    const int cg = tid % CG, rg = tid / CG;
    const int c0 = cg * 4, r0 = rg * 4;
    float acc[4][4];
#pragma unroll
    for (int j = 0; j < 4; j++)
#pragma unroll
        for (int i = 0; i < 4; i++) acc[j][i] = 0.f;

    for (int kc0 = 0; kc0 < K; kc0 += KC) {
        constexpr int NV = RPB * KC / 4;
#pragma unroll
        for (int v = 0; v < NV / 256; v++) {
            int idx = tid + v * 256;
            int r = idx / (KC / 4), kq = idx % (KC / 4);
            int gr = row0 + r;
            float4 x = make_float4(0.f, 0.f, 0.f, 0.f);
            if (gr < N) x = *(const float4*)&X[(long long)gr * K + kc0 + kq * 4];
            if (RELU) {
                x.x = fmaxf(x.x, 0.f); x.y = fmaxf(x.y, 0.f);
                x.z = fmaxf(x.z, 0.f); x.w = fmaxf(x.w, 0.f);
            }
            Xs[r][kq * 4 + 0] = x.x; Xs[r][kq * 4 + 1] = x.y;
            Xs[r][kq * 4 + 2] = x.z; Xs[r][kq * 4 + 3] = x.w;
        }
        __syncthreads();
#pragma unroll 4
        for (int k = 0; k < KC; k++) {
            float4 wb = *(const float4*)&Ws[(kc0 + k) * M + c0];
#pragma unroll
            for (int j = 0; j < 4; j++) {
                float xa = Xs[r0 + j][k];
                acc[j][0] = fmaf(xa, wb.x, acc[j][0]);
                acc[j][1] = fmaf(xa, wb.y, acc[j][1]);
                acc[j][2] = fmaf(xa, wb.z, acc[j][2]);
                acc[j][3] = fmaf(xa, wb.w, acc[j][3]);
            }
        }
        __syncthreads();
    }

#pragma unroll
    for (int j = 0; j < 4; j++) {
        int gr = row0 + r0 + j;
        if (gr < N)
            *(float4*)&Yraw[(long long)gr * M + c0] =
                make_float4(acc[j][0], acc[j][1], acc[j][2], acc[j][3]);
    }
}

// ---------------- CSR gather: out[d] = b + dinv[d]^2*hin[d] + sum_e w[e]*hin[src[e]] ----------------
// One warp per destination row. M=64: 2 cols/lane. M=32: 1 col/lane.
template <int M>
__global__ void __launch_bounds__(256)
k_gather(const float* __restrict__ hin, const float* __restrict__ bias,
         float* __restrict__ hout) {
    const int warp = (blockIdx.x * blockDim.x + threadIdx.x) >> 5;
    if (warp >= NP) return;
    const int lane = threadIdx.x & 31;
    const int beg = g_off[warp], end = g_off[warp + 1];

    if (M == 64) {
        float a0 = 0.f, a1 = 0.f;
        int e = beg;
        for (; e + 3 < end; e += 4) {
            int2 e0 = g_edge[e],     e1 = g_edge[e + 1];
            int2 e2 = g_edge[e + 2], e3 = g_edge[e + 3];
            float w0 = __int_as_float(e0.y), w1 = __int_as_float(e1.y);
            float w2 = __int_as_float(e2.y), w3 = __int_as_float(e3.y);
            float x00 = hin[e0.x * 64 + lane], x01 = hin[e0.x * 64 + 32 + lane];
            float x10 = hin[e1.x * 64 + lane], x11 = hin[e1.x * 64 + 32 + lane];
            float x20 = hin[e2.x * 64 + lane], x21 = hin[e2.x * 64 + 32 + lane];
            float x30 = hin[e3.x * 64 + lane], x31 = hin[e3.x * 64 + 32 + lane];
            a0 = fmaf(w0, x00, a0); a1 = fmaf(w0, x01, a1);
            a0 = fmaf(w1, x10, a0); a1 = fmaf(w1, x11, a1);
            a0 = fmaf(w2, x20, a0); a1 = fmaf(w2, x21, a1);
            a0 = fmaf(w3, x30, a0); a1 = fmaf(w3, x31, a1);
        }
        for (; e < end; e++) {
            int2 ed = g_edge[e];
            float w = __int_as_float(ed.y);
            a0 = fmaf(w, hin[ed.x * 64 + lane], a0);
            a1 = fmaf(w, hin[ed.x * 64 + 32 + lane], a1);
        }
        float di = g_dinv[warp], d2 = di * di;
        a0 += bias[lane]      + d2 * hin[warp * 64 + lane];
        a1 += bias[32 + lane] + d2 * hin[warp * 64 + 32 + lane];
        hout[warp * 64 + lane]      = a0;
        hout[warp * 64 + 32 + lane] = a1;
    } else {
        float a0 = 0.f;
        int e = beg;
        for (; e + 3 < end; e += 4) {
            int2 e0 = g_edge[e],     e1 = g_edge[e + 1];
            int2 e2 = g_edge[e + 2], e3 = g_edge[e + 3];
            a0 = fmaf(__int_as_float(e0.y), hin[e0.x * 32 + lane], a0);
            a0 = fmaf(__int_as_float(e1.y), hin[e1.x * 32 + lane], a0);
            a0 = fmaf(__int_as_float(e2.y), hin[e2.x * 32 + lane], a0);
            a0 = fmaf(__int_as_float(e3.y), hin[e3.x * 32 + lane], a0);
        }
        for (; e < end; e++) {
            int2 ed = g_edge[e];
            a0 = fmaf(__int_as_float(ed.y), hin[ed.x * 32 + lane], a0);
        }
        float di = g_dinv[warp], d2 = di * di;
        a0 += bias[lane] + d2 * hin[warp * 32 + lane];
        hout[warp * 32 + lane] = a0;
    }
}

// ---------------- drug aggregation (atomic; small) ----------------
__global__ void __launch_bounds__(256)
k_drug_agg(const int* __restrict__ pds, const int* __restrict__ pdd,
           const float* __restrict__ h) {
    int gid = blockIdx.x * blockDim.x + threadIdx.x;
    int e = gid / (D2 / 4);
    if (e >= EPD) return;
    int c = (gid % (D2 / 4)) * 4;
    int s = pds[e], d = pdd[e];
    float4 hv = *(const float4*)&h[s * D2 + c];
    red_add_v4(&g_agg[d * D2 + c], hv.x, hv.y, hv.z, hv.w);
    if (c == 0) atomicAdd(&g_cnt[d], 1.0f);
}

// ---------------- final drug GEMM: out = mean @ Wl + bl + x_drug @ Wr ----------------
__global__ void __launch_bounds__(256)
k_drug_out(const float* __restrict__ xd, const float* __restrict__ Wl,
           const float* __restrict__ bl, const float* __restrict__ Wr,
           float* __restrict__ out) {
    __shared__ float Wls[D2 * OUTD];
    __shared__ float Wrs[INP * OUTD];
    __shared__ float bls[OUTD];
    __shared__ float Ms[4 * D2];
    __shared__ float Xs[4 * INP];
    const int tid = threadIdx.x;
    for (int i = tid; i < D2 * OUTD; i += 256) Wls[i] = Wl[i];
    for (int i = tid; i < INP * OUTD; i += 256) Wrs[i] = Wr[i];
    if (tid < OUTD) bls[tid] = bl[tid];
    const int row0 = blockIdx.x * 4;
    for (int i = tid; i < 4 * D2; i += 256) {
        int r = row0 + i / D2;
        float cnt = fmaxf(g_cnt[r], 1.0f);
        Ms[i] = g_agg[r * D2 + (i % D2)] / cnt;
    }
    for (int i = tid; i < 4 * INP; i += 256)
        Xs[i] = xd[(row0 + i / INP) * INP + (i % INP)];
    __syncthreads();
    const int c = tid % OUTD;
    const int r = tid / OUTD;
    float acc = bls[c];
#pragma unroll
    for (int k = 0; k < D2; k++) acc = fmaf(Ms[r * D2 + k], Wls[k * OUTD + c], acc);
#pragma unroll 8
    for (int k = 0; k < INP; k++) acc = fmaf(Xs[r * INP + k], Wrs[k * OUTD + c], acc);
    out[(row0 + r) * OUTD + c] = acc;
}

// ---------------- host ----------------
extern "C" void kernel_launch(void* const* d_in, const int* in_sizes, int n_in,
                              void* d_out, int out_size) {
    const float *x_prot = 0, *x_drug = 0, *W1 = 0, *b1 = 0, *W2 = 0, *b2 = 0;
    const float *Wl = 0, *bl = 0, *Wr = 0;
    const int *pp = 0, *pds = 0, *pdd = 0;
    int n200k = 0, n8192 = 0, n64 = 0, n2048 = 0;
    for (int i = 0; i < n_in; i++) {
        int s = in_sizes[i];
        void* p = d_in[i];
        if (s == NP * INP)        x_prot = (const float*)p;
        else if (s == ND * INP)   x_drug = (const float*)p;
        else if (s == 2 * EPP)    pp = (const int*)p;
        else if (s == EPD) {      if (n200k++ == 0) pds = (const int*)p; else pdd = (const int*)p; }
        else if (s == INP * D1) { if (n8192++ == 0) W1 = (const float*)p; else Wr = (const float*)p; }
        else if (s == D1) {       if (n64++   == 0) b1 = (const float*)p; else bl = (const float*)p; }
        else if (s == D1 * D2) {  if (n2048++ == 0) W2 = (const float*)p; else Wl = (const float*)p; }
        else if (s == D2)         b2 = (const float*)p;
    }
    const int* pp_src = pp;
    const int* pp_dst = pp + EPP;
    float* h_out = (float*)d_out;                  // [NP, D2]
    float* drug_out = h_out + (long long)NP * D2;  // [ND, OUTD]

    float* g_h1_p; cudaGetSymbolAddress((void**)&g_h1_p, g_h1);
    float* g_o1_p; cudaGetSymbolAddress((void**)&g_o1_p, g_o1);
    float* g_h2_p; cudaGetSymbolAddress((void**)&g_h2_p, g_h2);

    // CSR build: degree -> 3-phase scan (dinv fused) -> place (weights fused)
    k_zero<<<256, 256>>>();
    k_degree<<<(EPP + 255) / 256, 256>>>(pp_dst);
    k_scan1<<<NB, SB>>>();
    k_scan2<<<1, SB>>>();
    k_scan3<<<NB, SB>>>();
    k_place<<<(EPP + 255) / 256, 256>>>(pp_src, pp_dst);

    // layer 1: gemm -> warp-per-row CSR gather (self-loop + bias fused)
    k_gemm<INP, D1, 32, false><<<(NP + 63) / 64, 256>>>(x_prot, W1, g_h1_p, NP);
    k_gather<D1><<<(NP * 32 + 255) / 256, 256>>>(g_h1_p, b1, g_o1_p);

    // layer 2: relu fused into gemm load -> gather straight into d_out
    k_gemm<D1, D2, 64, true><<<(NP + 127) / 128, 256>>>(g_o1_p, W2, g_h2_p, NP);
    k_gather<D2><<<(NP * 32 + 255) / 256, 256>>>(g_h2_p, b2, h_out);

    // bipartite mean-SAGE
    k_drug_agg<<<(EPD * (D2 / 4) + 255) / 256, 256>>>(pds, pdd, h_out);
    k_drug_out<<<ND / 4, 256>>>(x_drug, Wl, bl, Wr, drug_out);

    (void)out_size;
}

// round 5
// speedup vs baseline: 1.5126x; 1.0455x over previous
#include <cuda_runtime.h>

#define NP 50000          // N_PROT
#define ND 5000           // N_DRUG
#define EPP 1600000
#define EPD 200000
#define INP 128           // IN_PROT / IN_DRUG
#define D1 64
#define D2 32
#define OUTD 64

#define SB 256                          // scan block size
#define NB ((NP + SB - 1) / SB)         // 196 scan blocks

// ---------------- scratch (device globals: no allocation allowed) ----------------
__device__ int   g_deg[NP];
__device__ float g_dinv[NP];
__device__ int   g_bsum[NB];       // per-block degree sums
__device__ int   g_boff[NB];       // exclusive block offsets
__device__ int   g_off[NP + 1];    // CSR row offsets (by dst)
__device__ int   g_pos[NP];        // placement cursors
__device__ int2  g_edge[EPP];      // CSR: {src, bitcast(weight)}
__device__ float g_h1[NP * D1];    // x_prot @ W1 (raw)
__device__ float g_o1[NP * D1];    // propagated layer-1 output (pre-relu)
__device__ float g_h2[NP * D2];    // relu(o1) @ W2 (raw)
__device__ float g_agg[ND * D2];
__device__ float g_cnt[ND];

// ---------------- vector reduction helper (sm_90+) ----------------
__device__ __forceinline__ void red_add_v4(float* p, float x, float y, float z, float w) {
    asm volatile("red.global.add.v4.f32 [%0], {%1,%2,%3,%4};"
                 :: "l"(p), "f"(x), "f"(y), "f"(z), "f"(w) : "memory");
}

// ---------------- init / degree ----------------
__global__ void k_zero() {
    int gid = blockIdx.x * blockDim.x + threadIdx.x;
    int stride = gridDim.x * blockDim.x;
    for (int i = gid; i < NP; i += stride) g_deg[i] = 0;
    for (int i = gid; i < ND * D2; i += stride) g_agg[i] = 0.f;
    for (int i = gid; i < ND; i += stride) g_cnt[i] = 0.f;
}

__global__ void k_degree(const int* __restrict__ dst) {
    int e = blockIdx.x * blockDim.x + threadIdx.x;
    if (e < EPP) atomicAdd(&g_deg[dst[e]], 1);
}

// ---------------- 3-phase full-chip exclusive scan of g_deg ----------------
__global__ void __launch_bounds__(SB) k_scan1() {
    __shared__ int sh[SB / 32];
    int i = blockIdx.x * SB + threadIdx.x;
    int v = (i < NP) ? g_deg[i] : 0;
#pragma unroll
    for (int o = 16; o > 0; o >>= 1) v += __shfl_down_sync(0xffffffffu, v, o);
    if ((threadIdx.x & 31) == 0) sh[threadIdx.x >> 5] = v;
    __syncthreads();
    if (threadIdx.x < SB / 32) {
        int w = sh[threadIdx.x];
#pragma unroll
        for (int o = SB / 64; o > 0; o >>= 1) w += __shfl_down_sync(0xffffffffu, w, o);
        if (threadIdx.x == 0) g_bsum[blockIdx.x] = w;
    }
}

__global__ void __launch_bounds__(SB) k_scan2() {
    __shared__ int sh[SB];
    int t = threadIdx.x;
    int v = (t < NB) ? g_bsum[t] : 0;
    sh[t] = v;
    __syncthreads();
    for (int o = 1; o < SB; o <<= 1) {
        int u = (t >= o) ? sh[t - o] : 0;
        __syncthreads();
        sh[t] += u;
        __syncthreads();
    }
    if (t < NB) g_boff[t] = sh[t] - v;   // exclusive
}

__global__ void __launch_bounds__(SB) k_scan3() {
    __shared__ int sh[SB];
    int t = threadIdx.x;
    int i = blockIdx.x * SB + t;
    int v = (i < NP) ? g_deg[i] : 0;
    sh[t] = v;
    __syncthreads();
    for (int o = 1; o < SB; o <<= 1) {
        int u = (t >= o) ? sh[t - o] : 0;
        __syncthreads();
        sh[t] += u;
        __syncthreads();
    }
    if (i < NP) {
        int off = g_boff[blockIdx.x] + sh[t] - v;
        g_off[i] = off;
        g_pos[i] = off;
        g_dinv[i] = rsqrtf((float)v + 1.0f);   // +1 = self loop
    }
    if (i == NP - 1) g_off[NP] = EPP;
}

// ---------------- placement: counting-sort edges by dst, weight fused ----------------
__global__ void k_place(const int* __restrict__ src, const int* __restrict__ dst) {
    int e = blockIdx.x * blockDim.x + threadIdx.x;
    if (e >= EPP) return;
    int s = src[e], d = dst[e];
    int p = atomicAdd(&g_pos[d], 1);
    g_edge[p] = make_int2(s, __float_as_int(g_dinv[s] * g_dinv[d]));
}

// ---------------- GEMM: Yraw = (RELU? relu(X) : X) @ W ----------------
template <int K, int M, int KC, bool RELU>
__global__ void __launch_bounds__(256)
k_gemm(const float* __restrict__ X, const float* __restrict__ W,
       float* __restrict__ Yraw, int N) {
    constexpr int CG  = M / 4;
    constexpr int RG  = 256 / CG;
    constexpr int RPB = RG * 4;
    constexpr int KCP = KC + 2;
    __shared__ float Ws[K * M];
    __shared__ float Xs[RPB][KCP];

    const int tid = threadIdx.x;
    for (int i = tid; i < K * M; i += 256) Ws[i] = W[i];

    const int row0 = blockIdx.x * RPB;
    const int cg = tid % CG, rg = tid / CG;
    const int c0 = cg * 4, r0 = rg * 4;
    float acc[4][4];
#pragma unroll
    for (int j = 0; j < 4; j++)
#pragma unroll
        for (int i = 0; i < 4; i++) acc[j][i] = 0.f;

    for (int kc0 = 0; kc0 < K; kc0 += KC) {
        constexpr int NV = RPB * KC / 4;
#pragma unroll
        for (int v = 0; v < NV / 256; v++) {
            int idx = tid + v * 256;
            int r = idx / (KC / 4), kq = idx % (KC / 4);
            int gr = row0 + r;
            float4 x = make_float4(0.f, 0.f, 0.f, 0.f);
            if (gr < N) x = *(const float4*)&X[(long long)gr * K + kc0 + kq * 4];
            if (RELU) {
                x.x = fmaxf(x.x, 0.f); x.y = fmaxf(x.y, 0.f);
                x.z = fmaxf(x.z, 0.f); x.w = fmaxf(x.w, 0.f);
            }
            Xs[r][kq * 4 + 0] = x.x; Xs[r][kq * 4 + 1] = x.y;
            Xs[r][kq * 4 + 2] = x.z; Xs[r][kq * 4 + 3] = x.w;
        }
        __syncthreads();
#pragma unroll 4
        for (int k = 0; k < KC; k++) {
            float4 wb = *(const float4*)&Ws[(kc0 + k) * M + c0];
#pragma unroll
            for (int j = 0; j < 4; j++) {
                float xa = Xs[r0 + j][k];
                acc[j][0] = fmaf(xa, wb.x, acc[j][0]);
                acc[j][1] = fmaf(xa, wb.y, acc[j][1]);
                acc[j][2] = fmaf(xa, wb.z, acc[j][2]);
                acc[j][3] = fmaf(xa, wb.w, acc[j][3]);
            }
        }
        __syncthreads();
    }

#pragma unroll
    for (int j = 0; j < 4; j++) {
        int gr = row0 + r0 + j;
        if (gr < N)
            *(float4*)&Yraw[(long long)gr * M + c0] =
                make_float4(acc[j][0], acc[j][1], acc[j][2], acc[j][3]);
    }
}

// ---------------- CSR gather (M=64): float2/lane ----------------
__global__ void __launch_bounds__(256)
k_gather64(const float* __restrict__ hin, const float* __restrict__ bias,
           float* __restrict__ hout) {
    const int warp = (blockIdx.x * blockDim.x + threadIdx.x) >> 5;
    if (warp >= NP) return;
    const int lane = threadIdx.x & 31;
    const int beg = g_off[warp], end = g_off[warp + 1];
    const float2* __restrict__ hin2 = (const float2*)hin;
    const int col = lane;                    // float2 column

    float2 a = make_float2(0.f, 0.f);
    int e = beg;
    for (; e + 3 < end; e += 4) {
        int2 e0 = g_edge[e],     e1 = g_edge[e + 1];
        int2 e2 = g_edge[e + 2], e3 = g_edge[e + 3];
        float2 x0 = hin2[e0.x * 32 + col];
        float2 x1 = hin2[e1.x * 32 + col];
        float2 x2 = hin2[e2.x * 32 + col];
        float2 x3 = hin2[e3.x * 32 + col];
        float w0 = __int_as_float(e0.y), w1 = __int_as_float(e1.y);
        float w2 = __int_as_float(e2.y), w3 = __int_as_float(e3.y);
        a.x = fmaf(w0, x0.x, a.x); a.y = fmaf(w0, x0.y, a.y);
        a.x = fmaf(w1, x1.x, a.x); a.y = fmaf(w1, x1.y, a.y);
        a.x = fmaf(w2, x2.x, a.x); a.y = fmaf(w2, x2.y, a.y);
        a.x = fmaf(w3, x3.x, a.x); a.y = fmaf(w3, x3.y, a.y);
    }
    for (; e < end; e++) {
        int2 ed = g_edge[e];
        float w = __int_as_float(ed.y);
        float2 x = hin2[ed.x * 32 + col];
        a.x = fmaf(w, x.x, a.x);
        a.y = fmaf(w, x.y, a.y);
    }
    float di = g_dinv[warp], d2 = di * di;
    float2 self = hin2[warp * 32 + col];
    float2 bv = ((const float2*)bias)[col];
    a.x += bv.x + d2 * self.x;
    a.y += bv.y + d2 * self.y;
    ((float2*)hout)[warp * 32 + col] = a;
}

// ---------------- CSR gather (M=32): scalar/lane ----------------
__global__ void __launch_bounds__(256)
k_gather32(const float* __restrict__ hin, const float* __restrict__ bias,
           float* __restrict__ hout) {
    const int warp = (blockIdx.x * blockDim.x + threadIdx.x) >> 5;
    if (warp >= NP) return;
    const int lane = threadIdx.x & 31;
    const int beg = g_off[warp], end = g_off[warp + 1];

    float a0 = 0.f;
    int e = beg;
    for (; e + 3 < end; e += 4) {
        int2 e0 = g_edge[e],     e1 = g_edge[e + 1];
        int2 e2 = g_edge[e + 2], e3 = g_edge[e + 3];
        a0 = fmaf(__int_as_float(e0.y), hin[e0.x * 32 + lane], a0);
        a0 = fmaf(__int_as_float(e1.y), hin[e1.x * 32 + lane], a0);
        a0 = fmaf(__int_as_float(e2.y), hin[e2.x * 32 + lane], a0);
        a0 = fmaf(__int_as_float(e3.y), hin[e3.x * 32 + lane], a0);
    }
    for (; e < end; e++) {
        int2 ed = g_edge[e];
        a0 = fmaf(__int_as_float(ed.y), hin[ed.x * 32 + lane], a0);
    }
    float di = g_dinv[warp], d2 = di * di;
    a0 += bias[lane] + d2 * hin[warp * 32 + lane];
    hout[warp * 32 + lane] = a0;
}

// ---------------- drug aggregation (atomic; small) ----------------
__global__ void __launch_bounds__(256)
k_drug_agg(const int* __restrict__ pds, const int* __restrict__ pdd,
           const float* __restrict__ h) {
    int gid = blockIdx.x * blockDim.x + threadIdx.x;
    int e = gid / (D2 / 4);
    if (e >= EPD) return;
    int c = (gid % (D2 / 4)) * 4;
    int s = pds[e], d = pdd[e];
    float4 hv = *(const float4*)&h[s * D2 + c];
    red_add_v4(&g_agg[d * D2 + c], hv.x, hv.y, hv.z, hv.w);
    if (c == 0) atomicAdd(&g_cnt[d], 1.0f);
}

// ---------------- final drug GEMM: out = mean @ Wl + bl + x_drug @ Wr ----------------
__global__ void __launch_bounds__(256)
k_drug_out(const float* __restrict__ xd, const float* __restrict__ Wl,
           const float* __restrict__ bl, const float* __restrict__ Wr,
           float* __restrict__ out) {
    __shared__ float Wls[D2 * OUTD];
    __shared__ float Wrs[INP * OUTD];
    __shared__ float bls[OUTD];
    __shared__ float Ms[4 * D2];
    __shared__ float Xs[4 * INP];
    const int tid = threadIdx.x;
    for (int i = tid; i < D2 * OUTD; i += 256) Wls[i] = Wl[i];
    for (int i = tid; i < INP * OUTD; i += 256) Wrs[i] = Wr[i];
    if (tid < OUTD) bls[tid] = bl[tid];
    const int row0 = blockIdx.x * 4;
    for (int i = tid; i < 4 * D2; i += 256) {
        int r = row0 + i / D2;
        float cnt = fmaxf(g_cnt[r], 1.0f);
        Ms[i] = g_agg[r * D2 + (i % D2)] / cnt;
    }
    for (int i = tid; i < 4 * INP; i += 256)
        Xs[i] = xd[(row0 + i / INP) * INP + (i % INP)];
    __syncthreads();
    const int c = tid % OUTD;
    const int r = tid / OUTD;
    float acc = bls[c];
#pragma unroll
    for (int k = 0; k < D2; k++) acc = fmaf(Ms[r * D2 + k], Wls[k * OUTD + c], acc);
#pragma unroll 8
    for (int k = 0; k < INP; k++) acc = fmaf(Xs[r * INP + k], Wrs[k * OUTD + c], acc);
    out[(row0 + r) * OUTD + c] = acc;
}

// ---------------- host ----------------
extern "C" void kernel_launch(void* const* d_in, const int* in_sizes, int n_in,
                              void* d_out, int out_size) {
    const float *x_prot = 0, *x_drug = 0, *W1 = 0, *b1 = 0, *W2 = 0, *b2 = 0;
    const float *Wl = 0, *bl = 0, *Wr = 0;
    const int *pp = 0, *pds = 0, *pdd = 0;
    int n200k = 0, n8192 = 0, n64 = 0, n2048 = 0;
    for (int i = 0; i < n_in; i++) {
        int s = in_sizes[i];
        void* p = d_in[i];
        if (s == NP * INP)        x_prot = (const float*)p;
        else if (s == ND * INP)   x_drug = (const float*)p;
        else if (s == 2 * EPP)    pp = (const int*)p;
        else if (s == EPD) {      if (n200k++ == 0) pds = (const int*)p; else pdd = (const int*)p; }
        else if (s == INP * D1) { if (n8192++ == 0) W1 = (const float*)p; else Wr = (const float*)p; }
        else if (s == D1) {       if (n64++   == 0) b1 = (const float*)p; else bl = (const float*)p; }
        else if (s == D1 * D2) {  if (n2048++ == 0) W2 = (const float*)p; else Wl = (const float*)p; }
        else if (s == D2)         b2 = (const float*)p;
    }
    const int* pp_src = pp;
    const int* pp_dst = pp + EPP;
    float* h_out = (float*)d_out;                  // [NP, D2]
    float* drug_out = h_out + (long long)NP * D2;  // [ND, OUTD]

    float* g_h1_p; cudaGetSymbolAddress((void**)&g_h1_p, g_h1);
    float* g_o1_p; cudaGetSymbolAddress((void**)&g_o1_p, g_o1);
    float* g_h2_p; cudaGetSymbolAddress((void**)&g_h2_p, g_h2);

    // One-time side-stream + events for fork/join inside graph capture.
    // (No device memory involved; identical GPU work on every call.)
    static cudaStream_t s2 = 0;
    static cudaEvent_t evFork = 0, evJoin = 0;
    static int sideOk = -1;
    if (sideOk < 0) {
        sideOk = (cudaStreamCreateWithFlags(&s2, cudaStreamNonBlocking) == cudaSuccess &&
                  cudaEventCreateWithFlags(&evFork, cudaEventDisableTiming) == cudaSuccess &&
                  cudaEventCreateWithFlags(&evJoin, cudaEventDisableTiming) == cudaSuccess) ? 1 : 0;
    }

    if (sideOk) {
        // fork: CSR build on s2, gemm1 on main stream, join before gather1
        cudaEventRecord(evFork, 0);
        cudaStreamWaitEvent(s2, evFork, 0);

        k_zero<<<256, 256, 0, s2>>>();
        k_degree<<<(EPP + 255) / 256, 256, 0, s2>>>(pp_dst);
        k_scan1<<<NB, SB, 0, s2>>>();
        k_scan2<<<1, SB, 0, s2>>>();
        k_scan3<<<NB, SB, 0, s2>>>();
        k_place<<<(EPP + 255) / 256, 256, 0, s2>>>(pp_src, pp_dst);
        cudaEventRecord(evJoin, s2);

        k_gemm<INP, D1, 32, false><<<(NP + 63) / 64, 256>>>(x_prot, W1, g_h1_p, NP);
        cudaStreamWaitEvent(0, evJoin, 0);
    } else {
        k_zero<<<256, 256>>>();
        k_degree<<<(EPP + 255) / 256, 256>>>(pp_dst);
        k_scan1<<<NB, SB>>>();
        k_scan2<<<1, SB>>>();
        k_scan3<<<NB, SB>>>();
        k_place<<<(EPP + 255) / 256, 256>>>(pp_src, pp_dst);
        k_gemm<INP, D1, 32, false><<<(NP + 63) / 64, 256>>>(x_prot, W1, g_h1_p, NP);
    }

    // layer 1 propagate -> layer 2 gemm -> propagate into d_out
    k_gather64<<<(NP * 32 + 255) / 256, 256>>>(g_h1_p, b1, g_o1_p);
    k_gemm<D1, D2, 64, true><<<(NP + 127) / 128, 256>>>(g_o1_p, W2, g_h2_p, NP);
    k_gather32<<<(NP * 32 + 255) / 256, 256>>>(g_h2_p, b2, h_out);

    // bipartite mean-SAGE
    k_drug_agg<<<(EPD * (D2 / 4) + 255) / 256, 256>>>(pds, pdd, h_out);
    k_drug_out<<<ND / 4, 256>>>(x_drug, Wl, bl, Wr, drug_out);

    (void)out_size;
}

// round 7
// speedup vs baseline: 1.6226x; 1.0727x over previous
#include <cuda_runtime.h>
#include <cuda_fp16.h>

#define NP 50000          // N_PROT
#define ND 5000           // N_DRUG
#define EPP 1600000
#define EPD 200000
#define INP 128           // IN_PROT / IN_DRUG
#define D1 64
#define D2 32
#define OUTD 64

#define SB 256                          // scan block size
#define NB ((NP + SB - 1) / SB)         // 196 scan blocks

// ---------------- scratch (device globals: no allocation allowed) ----------------
__device__ int    g_deg[NP];
__device__ float  g_dinv[NP];
__device__ int    g_bsum[NB];
__device__ int    g_boff[NB];
__device__ int    g_off[NP + 1];    // CSR row offsets (by dst)
__device__ int    g_pos[NP];        // placement cursors
__device__ int2   g_edge[EPP];      // CSR: {src, bitcast(weight)}
__device__ __half g_h1[NP * D1];    // x_prot @ W1 (raw, fp16)
__device__ float  g_o1[NP * D1];    // propagated layer-1 output (pre-relu, fp32)
__device__ __half g_h2[NP * D2];    // relu(o1) @ W2 (raw, fp16)
__device__ float  g_agg[ND * D2];
__device__ float  g_cnt[ND];
__device__ float  g_xr[ND * OUTD];  // x_drug @ Wr + bl (precomputed)

// ---------------- vector reduction helper (sm_90+) ----------------
__device__ __forceinline__ void red_add_v4(float* p, float x, float y, float z, float w) {
    asm volatile("red.global.add.v4.f32 [%0], {%1,%2,%3,%4};"
                 :: "l"(p), "f"(x), "f"(y), "f"(z), "f"(w) : "memory");
}

// ---------------- init / degree ----------------
__global__ void k_zero() {
    int gid = blockIdx.x * blockDim.x + threadIdx.x;
    int stride = gridDim.x * blockDim.x;
    for (int i = gid; i < NP; i += stride) g_deg[i] = 0;
    for (int i = gid; i < ND * D2; i += stride) g_agg[i] = 0.f;
    for (int i = gid; i < ND; i += stride) g_cnt[i] = 0.f;
}

__global__ void k_degree(const int* __restrict__ dst) {
    int e = blockIdx.x * blockDim.x + threadIdx.x;
    if (e < EPP) atomicAdd(&g_deg[dst[e]], 1);
}

// ---------------- 3-phase full-chip exclusive scan of g_deg ----------------
__global__ void __launch_bounds__(SB) k_scan1() {
    __shared__ int sh[SB / 32];
    int i = blockIdx.x * SB + threadIdx.x;
    int v = (i < NP) ? g_deg[i] : 0;
#pragma unroll
    for (int o = 16; o > 0; o >>= 1) v += __shfl_down_sync(0xffffffffu, v, o);
    if ((threadIdx.x & 31) == 0) sh[threadIdx.x >> 5] = v;
    __syncthreads();
    if (threadIdx.x < SB / 32) {
        int w = sh[threadIdx.x];
#pragma unroll
        for (int o = SB / 64; o > 0; o >>= 1) w += __shfl_down_sync(0xffffffffu, w, o);
        if (threadIdx.x == 0) g_bsum[blockIdx.x] = w;
    }
}

__global__ void __launch_bounds__(SB) k_scan2() {
    __shared__ int sh[SB];
    int t = threadIdx.x;
    int v = (t < NB) ? g_bsum[t] : 0;
    sh[t] = v;
    __syncthreads();
    for (int o = 1; o < SB; o <<= 1) {
        int u = (t >= o) ? sh[t - o] : 0;
        __syncthreads();
        sh[t] += u;
        __syncthreads();
    }
    if (t < NB) g_boff[t] = sh[t] - v;   // exclusive
}

__global__ void __launch_bounds__(SB) k_scan3() {
    __shared__ int sh[SB];
    int t = threadIdx.x;
    int i = blockIdx.x * SB + t;
    int v = (i < NP) ? g_deg[i] : 0;
    sh[t] = v;
    __syncthreads();
    for (int o = 1; o < SB; o <<= 1) {
        int u = (t >= o) ? sh[t - o] : 0;
        __syncthreads();
        sh[t] += u;
        __syncthreads();
    }
    if (i < NP) {
        int off = g_boff[blockIdx.x] + sh[t] - v;
        g_off[i] = off;
        g_pos[i] = off;
        g_dinv[i] = rsqrtf((float)v + 1.0f);   // +1 = self loop
    }
    if (i == NP - 1) g_off[NP] = EPP;
}

// ---------------- placement: counting-sort edges by dst, weight fused ----------------
__global__ void k_place(const int* __restrict__ src, const int* __restrict__ dst) {
    int e = blockIdx.x * blockDim.x + threadIdx.x;
    if (e >= EPP) return;
    int s = src[e], d = dst[e];
    int p = atomicAdd(&g_pos[d], 1);
    g_edge[p] = make_int2(s, __float_as_int(g_dinv[s] * g_dinv[d]));
}

// ---------------- GEMM: Y = (RELU? relu(X) : X) @ W, output fp16 ----------------
template <int K, int M, int KC, bool RELU>
__global__ void __launch_bounds__(256)
k_gemm_h(const float* __restrict__ X, const float* __restrict__ W,
         __half* __restrict__ Y, int N) {
    constexpr int CG  = M / 4;
    constexpr int RG  = 256 / CG;
    constexpr int RPB = RG * 4;
    constexpr int KCP = KC + 2;
    __shared__ float Ws[K * M];
    __shared__ float Xs[RPB][KCP];

    const int tid = threadIdx.x;
    for (int i = tid; i < K * M; i += 256) Ws[i] = W[i];

    const int row0 = blockIdx.x * RPB;
    const int cg = tid % CG, rg = tid / CG;
    const int c0 = cg * 4, r0 = rg * 4;
    float acc[4][4];
#pragma unroll
    for (int j = 0; j < 4; j++)
#pragma unroll
        for (int i = 0; i < 4; i++) acc[j][i] = 0.f;

    for (int kc0 = 0; kc0 < K; kc0 += KC) {
        constexpr int NV = RPB * KC / 4;
#pragma unroll
        for (int v = 0; v < NV / 256; v++) {
            int idx = tid + v * 256;
            int r = idx / (KC / 4), kq = idx % (KC / 4);
            int gr = row0 + r;
            float4 x = make_float4(0.f, 0.f, 0.f, 0.f);
            if (gr < N) x = *(const float4*)&X[(long long)gr * K + kc0 + kq * 4];
            if (RELU) {
                x.x = fmaxf(x.x, 0.f); x.y = fmaxf(x.y, 0.f);
                x.z = fmaxf(x.z, 0.f); x.w = fmaxf(x.w, 0.f);
            }
            Xs[r][kq * 4 + 0] = x.x; Xs[r][kq * 4 + 1] = x.y;
            Xs[r][kq * 4 + 2] = x.z; Xs[r][kq * 4 + 3] = x.w;
        }
        __syncthreads();
#pragma unroll 4
        for (int k = 0; k < KC; k++) {
            float4 wb = *(const float4*)&Ws[(kc0 + k) * M + c0];
#pragma unroll
            for (int j = 0; j < 4; j++) {
                float xa = Xs[r0 + j][k];
                acc[j][0] = fmaf(xa, wb.x, acc[j][0]);
                acc[j][1] = fmaf(xa, wb.y, acc[j][1]);
                acc[j][2] = fmaf(xa, wb.z, acc[j][2]);
                acc[j][3] = fmaf(xa, wb.w, acc[j][3]);
            }
        }
        __syncthreads();
    }

#pragma unroll
    for (int j = 0; j < 4; j++) {
        int gr = row0 + r0 + j;
        if (gr < N) {
            __half2 p0 = __floats2half2_rn(acc[j][0], acc[j][1]);
            __half2 p1 = __floats2half2_rn(acc[j][2], acc[j][3]);
            uint2 pk;
            pk.x = *(unsigned int*)&p0;
            pk.y = *(unsigned int*)&p1;
            *(uint2*)(Y + (long long)gr * M + c0) = pk;
        }
    }
}

// ---------------- CSR gather (M=64, fp16 in): warp/row, half2/lane ----------------
__global__ void __launch_bounds__(256)
k_gather64h(const __half* __restrict__ hin, const float* __restrict__ bias,
            float* __restrict__ hout) {
    const int warp = (blockIdx.x * blockDim.x + threadIdx.x) >> 5;
    if (warp >= NP) return;
    const int lane = threadIdx.x & 31;
    const int beg = g_off[warp], end = g_off[warp + 1];
    const __half2* __restrict__ h2 = (const __half2*)hin;   // row stride 32

    float2 a = make_float2(0.f, 0.f);
    int e = beg;
    for (; e + 3 < end; e += 4) {
        int2 e0 = g_edge[e],     e1 = g_edge[e + 1];
        int2 e2 = g_edge[e + 2], e3 = g_edge[e + 3];
        float2 x0 = __half22float2(h2[e0.x * 32 + lane]);
        float2 x1 = __half22float2(h2[e1.x * 32 + lane]);
        float2 x2 = __half22float2(h2[e2.x * 32 + lane]);
        float2 x3 = __half22float2(h2[e3.x * 32 + lane]);
        float w0 = __int_as_float(e0.y), w1 = __int_as_float(e1.y);
        float w2 = __int_as_float(e2.y), w3 = __int_as_float(e3.y);
        a.x = fmaf(w0, x0.x, a.x); a.y = fmaf(w0, x0.y, a.y);
        a.x = fmaf(w1, x1.x, a.x); a.y = fmaf(w1, x1.y, a.y);
        a.x = fmaf(w2, x2.x, a.x); a.y = fmaf(w2, x2.y, a.y);
        a.x = fmaf(w3, x3.x, a.x); a.y = fmaf(w3, x3.y, a.y);
    }
    for (; e < end; e++) {
        int2 ed = g_edge[e];
        float w = __int_as_float(ed.y);
        float2 x = __half22float2(h2[ed.x * 32 + lane]);
        a.x = fmaf(w, x.x, a.x);
        a.y = fmaf(w, x.y, a.y);
    }
    float di = g_dinv[warp], d2 = di * di;
    float2 self = __half22float2(h2[warp * 32 + lane]);
    float2 bv = ((const float2*)bias)[lane];
    a.x += bv.x + d2 * self.x;
    a.y += bv.y + d2 * self.y;
    ((float2*)hout)[warp * 32 + lane] = a;
}

// ---------------- CSR gather (M=32, fp16 in): half-warp/row, half2/lane ----------------
__global__ void __launch_bounds__(256)
k_gather32h(const __half* __restrict__ hin, const float* __restrict__ bias,
            float* __restrict__ hout) {
    const int gw = (blockIdx.x * blockDim.x + threadIdx.x) >> 5;
    const int lane = threadIdx.x & 31;
    const int row = gw * 2 + (lane >> 4);
    if (row >= NP) return;
    const int col = lane & 15;
    const int beg = g_off[row], end = g_off[row + 1];
    const __half2* __restrict__ h2 = (const __half2*)hin;   // row stride 16

    float2 a = make_float2(0.f, 0.f);
    int e = beg;
    for (; e + 3 < end; e += 4) {
        int2 e0 = g_edge[e],     e1 = g_edge[e + 1];
        int2 e2 = g_edge[e + 2], e3 = g_edge[e + 3];
        float2 x0 = __half22float2(h2[e0.x * 16 + col]);
        float2 x1 = __half22float2(h2[e1.x * 16 + col]);
        float2 x2 = __half22float2(h2[e2.x * 16 + col]);
        float2 x3 = __half22float2(h2[e3.x * 16 + col]);
        float w0 = __int_as_float(e0.y), w1 = __int_as_float(e1.y);
        float w2 = __int_as_float(e2.y), w3 = __int_as_float(e3.y);
        a.x = fmaf(w0, x0.x, a.x); a.y = fmaf(w0, x0.y, a.y);
        a.x = fmaf(w1, x1.x, a.x); a.y = fmaf(w1, x1.y, a.y);
        a.x = fmaf(w2, x2.x, a.x); a.y = fmaf(w2, x2.y, a.y);
        a.x = fmaf(w3, x3.x, a.x); a.y = fmaf(w3, x3.y, a.y);
    }
    for (; e < end; e++) {
        int2 ed = g_edge[e];
        float w = __int_as_float(ed.y);
        float2 x = __half22float2(h2[ed.x * 16 + col]);
        a.x = fmaf(w, x.x, a.x);
        a.y = fmaf(w, x.y, a.y);
    }
    float di = g_dinv[row], d2 = di * di;
    float2 self = __half22float2(h2[row * 16 + col]);
    float2 bv = ((const float2*)bias)[col];
    a.x += bv.x + d2 * self.x;
    a.y += bv.y + d2 * self.y;
    ((float2*)hout)[row * 16 + col] = a;
}

// ---------------- drug aggregation (atomic; small) ----------------
__global__ void __launch_bounds__(256)
k_drug_agg(const int* __restrict__ pds, const int* __restrict__ pdd,
           const float* __restrict__ h) {
    int gid = blockIdx.x * blockDim.x + threadIdx.x;
    int e = gid / (D2 / 4);
    if (e >= EPD) return;
    int c = (gid % (D2 / 4)) * 4;
    int s = pds[e], d = pdd[e];
    float4 hv = *(const float4*)&h[s * D2 + c];
    red_add_v4(&g_agg[d * D2 + c], hv.x, hv.y, hv.z, hv.w);
    if (c == 0) atomicAdd(&g_cnt[d], 1.0f);
}

// ---------------- precompute: g_xr = x_drug @ Wr + bl (off critical path) ----------------
__global__ void __launch_bounds__(256)
k_drug_xr(const float* __restrict__ xd, const float* __restrict__ Wr,
          const float* __restrict__ bl) {
    __shared__ float Wrs[INP * OUTD];   // 32KB
    __shared__ float Xs[4 * INP];
    const int tid = threadIdx.x;
    for (int i = tid; i < INP * OUTD; i += 256) Wrs[i] = Wr[i];
    const int row0 = blockIdx.x * 4;
    for (int i = tid; i < 4 * INP; i += 256)
        Xs[i] = xd[(row0 + i / INP) * INP + (i % INP)];
    __syncthreads();
    const int c = tid % OUTD;
    const int r = tid / OUTD;
    float acc = bl[c];
#pragma unroll 8
    for (int k = 0; k < INP; k++) acc = fmaf(Xs[r * INP + k], Wrs[k * OUTD + c], acc);
    g_xr[(row0 + r) * OUTD + c] = acc;
}

// ---------------- final: out = mean @ Wl + g_xr ----------------
__global__ void __launch_bounds__(256)
k_drug_out(const float* __restrict__ Wl, float* __restrict__ out) {
    __shared__ float Wls[D2 * OUTD];   // 8KB
    __shared__ float Ms[4 * D2];
    const int tid = threadIdx.x;
    for (int i = tid; i < D2 * OUTD; i += 256) Wls[i] = Wl[i];
    const int row0 = blockIdx.x * 4;
    for (int i = tid; i < 4 * D2; i += 256) {
        int r = row0 + i / D2;
        float cnt = fmaxf(g_cnt[r], 1.0f);
        Ms[i] = g_agg[r * D2 + (i % D2)] / cnt;
    }
    __syncthreads();
    const int c = tid % OUTD;
    const int r = tid / OUTD;
    float acc = g_xr[(row0 + r) * OUTD + c];
#pragma unroll
    for (int k = 0; k < D2; k++) acc = fmaf(Ms[r * D2 + k], Wls[k * OUTD + c], acc);
    out[(row0 + r) * OUTD + c] = acc;
}

// ---------------- host ----------------
extern "C" void kernel_launch(void* const* d_in, const int* in_sizes, int n_in,
                              void* d_out, int out_size) {
    const float *x_prot = 0, *x_drug = 0, *W1 = 0, *b1 = 0, *W2 = 0, *b2 = 0;
    const float *Wl = 0, *bl = 0, *Wr = 0;
    const int *pp = 0, *pds = 0, *pdd = 0;
    int n200k = 0, n8192 = 0, n64 = 0, n2048 = 0;
    for (int i = 0; i < n_in; i++) {
        int s = in_sizes[i];
        void* p = d_in[i];
        if (s == NP * INP)        x_prot = (const float*)p;
        else if (s == ND * INP)   x_drug = (const float*)p;
        else if (s == 2 * EPP)    pp = (const int*)p;
        else if (s == EPD) {      if (n200k++ == 0) pds = (const int*)p; else pdd = (const int*)p; }
        else if (s == INP * D1) { if (n8192++ == 0) W1 = (const float*)p; else Wr = (const float*)p; }
        else if (s == D1) {       if (n64++   == 0) b1 = (const float*)p; else bl = (const float*)p; }
        else if (s == D1 * D2) {  if (n2048++ == 0) W2 = (const float*)p; else Wl = (const float*)p; }
        else if (s == D2)         b2 = (const float*)p;
    }
    const int* pp_src = pp;
    const int* pp_dst = pp + EPP;
    float* h_out = (float*)d_out;                  // [NP, D2]
    float* drug_out = h_out + (long long)NP * D2;  // [ND, OUTD]

    __half* g_h1_p; cudaGetSymbolAddress((void**)&g_h1_p, g_h1);
    float*  g_o1_p; cudaGetSymbolAddress((void**)&g_o1_p, g_o1);
    __half* g_h2_p; cudaGetSymbolAddress((void**)&g_h2_p, g_h2);

    static cudaStream_t s2 = 0;
    static cudaEvent_t evFork = 0, evJoin = 0, evJoin2 = 0;
    static int sideOk = -1;
    if (sideOk < 0) {
        sideOk = (cudaStreamCreateWithFlags(&s2, cudaStreamNonBlocking) == cudaSuccess &&
                  cudaEventCreateWithFlags(&evFork, cudaEventDisableTiming) == cudaSuccess &&
                  cudaEventCreateWithFlags(&evJoin, cudaEventDisableTiming) == cudaSuccess &&
                  cudaEventCreateWithFlags(&evJoin2, cudaEventDisableTiming) == cudaSuccess) ? 1 : 0;
    }

    if (sideOk) {
        cudaEventRecord(evFork, 0);
        cudaStreamWaitEvent(s2, evFork, 0);

        // side stream: CSR build, then drug xr precompute
        k_zero<<<256, 256, 0, s2>>>();
        k_degree<<<(EPP + 255) / 256, 256, 0, s2>>>(pp_dst);
        k_scan1<<<NB, SB, 0, s2>>>();
        k_scan2<<<1, SB, 0, s2>>>();
        k_scan3<<<NB, SB, 0, s2>>>();
        k_place<<<(EPP + 255) / 256, 256, 0, s2>>>(pp_src, pp_dst);
        cudaEventRecord(evJoin, s2);
        k_drug_xr<<<ND / 4, 256, 0, s2>>>(x_drug, Wr, bl);
        cudaEventRecord(evJoin2, s2);

        // main stream: gemm1 in parallel with CSR build
        k_gemm_h<INP, D1, 32, false><<<(NP + 63) / 64, 256>>>(x_prot, W1, g_h1_p, NP);
        cudaStreamWaitEvent(0, evJoin, 0);

        k_gather64h<<<(NP * 32 + 255) / 256, 256>>>(g_h1_p, b1, g_o1_p);
        k_gemm_h<D1, D2, 64, true><<<(NP + 127) / 128, 256>>>(g_o1_p, W2, g_h2_p, NP);
        k_gather32h<<<(NP / 2 * 32 + 255) / 256, 256>>>(g_h2_p, b2, h_out);
        k_drug_agg<<<(EPD * (D2 / 4) + 255) / 256, 256>>>(pds, pdd, h_out);
        cudaStreamWaitEvent(0, evJoin2, 0);
        k_drug_out<<<ND / 4, 256>>>(Wl, drug_out);
    } else {
        k_zero<<<256, 256>>>();
        k_degree<<<(EPP + 255) / 256, 256>>>(pp_dst);
        k_scan1<<<NB, SB>>>();
        k_scan2<<<1, SB>>>();
        k_scan3<<<NB, SB>>>();
        k_place<<<(EPP + 255) / 256, 256>>>(pp_src, pp_dst);
        k_gemm_h<INP, D1, 32, false><<<(NP + 63) / 64, 256>>>(x_prot, W1, g_h1_p, NP);
        k_gather64h<<<(NP * 32 + 255) / 256, 256>>>(g_h1_p, b1, g_o1_p);
        k_gemm_h<D1, D2, 64, true><<<(NP + 127) / 128, 256>>>(g_o1_p, W2, g_h2_p, NP);
        k_gather32h<<<(NP / 2 * 32 + 255) / 256, 256>>>(g_h2_p, b2, h_out);
        k_drug_agg<<<(EPD * (D2 / 4) + 255) / 256, 256>>>(pds, pdd, h_out);
        k_drug_xr<<<ND / 4, 256>>>(x_drug, Wr, bl);
        k_drug_out<<<ND / 4, 256>>>(Wl, drug_out);
    }

    (void)out_size;
}